// round 8
// baseline (speedup 1.0000x reference)
#include <cuda_runtime.h>
#include <cstdint>

#define NB 256
#define NS 512
#define ND 256
#define NA 128
#define TS 128
#define NTILE 4
#define KC 32
#define NCHUNK 8
#define NT 512

// ---- scratch (allocation-free rule: device globals) ----
__device__ float  g_part[NB * NTILE * ND];
__device__ float  g_esum[NB * NTILE];
__device__ int8_t g_w8h[NCHUNK * NA * KC];   // [c][n][k] int8 hi limb
__device__ int8_t g_w8l[NCHUNK * NA * KC];   // lo limb
__device__ float  g_winv[NA];                // per-column inverse scale

// ---- smem layout (bytes) ----
#define S_ES    0
#define S_BSM   512
#define S_USM   1024
#define S_WINV  1536
#define S_RED   2048
#define S_SXI(b) (2560 + (b) * 512)          // inv_sx per row, double-buffered
#define S_AH(b) (4096 + (b) * 12288)         // 128 rows * 48B
#define S_AL(b) (S_AH(b) + 6144)
#define S_BH(b) (28672 + (b) * 12288)
#define S_BL(b) (S_BH(b) + 6144)
#define S_SCR   4096                          // reuse A region post-loop
#define SMEM_TOTAL 53248

#define LDSM4(r, addr) \
    asm volatile("ldmatrix.sync.aligned.m8n8.x4.shared.b16 {%0,%1,%2,%3}, [%4];" \
        : "=r"((r)[0]), "=r"((r)[1]), "=r"((r)[2]), "=r"((r)[3]) : "r"(addr))

#define MMA_S8_ZERO(d, a, b0, b1) \
    asm volatile("mma.sync.aligned.m16n8k32.row.col.s32.s8.s8.s32 " \
        "{%0,%1,%2,%3},{%4,%5,%6,%7},{%8,%9},{%10,%10,%10,%10};" \
        : "=r"((d)[0]), "=r"((d)[1]), "=r"((d)[2]), "=r"((d)[3]) \
        : "r"((a)[0]), "r"((a)[1]), "r"((a)[2]), "r"((a)[3]), "r"(b0), "r"(b1), "r"(0))

#define MMA_S8_ACC(d, a, b0, b1) \
    asm volatile("mma.sync.aligned.m16n8k32.row.col.s32.s8.s8.s32 " \
        "{%0,%1,%2,%3},{%4,%5,%6,%7},{%8,%9},{%0,%1,%2,%3};" \
        : "+r"((d)[0]), "+r"((d)[1]), "+r"((d)[2]), "+r"((d)[3]) \
        : "r"((a)[0]), "r"((a)[1]), "r"((a)[2]), "r"((a)[3]), "r"(b0), "r"(b1))

__device__ __forceinline__ void cp16(char* dst, const char* src) {
    unsigned saddr = (unsigned)__cvta_generic_to_shared(dst);
    asm volatile("cp.async.cg.shared.global [%0], [%1], 16;\n" :: "r"(saddr), "l"(src));
}
__device__ __forceinline__ void cp_commit() { asm volatile("cp.async.commit_group;\n"); }
template<int N> __device__ __forceinline__ void cp_wait() {
    asm volatile("cp.async.wait_group %0;\n" :: "n"(N));
}
__device__ __forceinline__ float fast_tanh(float x) {
    float e = __expf(2.0f * x);
    return 1.0f - __fdividef(2.0f, e + 1.0f);
}

// ---------------------------------------------------------------------------
// W prep: per-column int16 quantization, split into int8 limbs [c][n][k].
// ---------------------------------------------------------------------------
__global__ void __launch_bounds__(256) wprep_kernel(const float* __restrict__ W) {
    __shared__ float sm[256];
    const int n = blockIdx.x;      // att col
    const int k = threadIdx.x;     // d row
    float w = W[(size_t)k * NA + n];
    sm[k] = fabsf(w);
    __syncthreads();
    for (int st = 128; st > 0; st >>= 1) {
        if (k < st) sm[k] = fmaxf(sm[k], sm[k + st]);
        __syncthreads();
    }
    float colmax = fmaxf(sm[0], 1e-30f);
    float s = __fdividef(32256.0f, colmax);
    int X = __float2int_rn(w * s);
    int hh = (X + 128) >> 8;
    int ll = X - (hh << 8);
    int c = k >> 5, kk = k & 31;
    g_w8h[(size_t)c * NA * KC + n * KC + kk] = (int8_t)hh;
    g_w8l[(size_t)c * NA * KC + n * KC + kk] = (int8_t)ll;
    if (k == 0) g_winv[n] = colmax * (1.0f / 32256.0f);
}

// ---------------------------------------------------------------------------
// Scores: int8 IMMA 3-pass (hh, hl, lh) with per-(row,chunk) x scales and
// per-chunk f32 descale; fused tanh/dot(u)/exp + weighted partial sum.
// 512 threads, warp tile 16(M) x 64(N).
// ---------------------------------------------------------------------------
__global__ void __launch_bounds__(NT, 1) scores_kernel(
    const float* __restrict__ x, const float* __restrict__ bias,
    const float* __restrict__ u)
{
    extern __shared__ char smem[];
    const uint32_t smb = (uint32_t)__cvta_generic_to_shared(smem);

    const int bid  = blockIdx.x;
    const int tile = bid & 3;
    const int b    = bid >> 2;
    const int tid  = threadIdx.x;
    const int w    = tid >> 5;
    const int l    = tid & 31;
    const int wm   = w >> 1;        // 0..7 : rows wm*16
    const int wn   = w & 1;         // 0..1 : cols wn*64

    float* es   = (float*)(smem + S_ES);
    float* bsm  = (float*)(smem + S_BSM);
    float* usm  = (float*)(smem + S_USM);
    float* winv = (float*)(smem + S_WINV);
    float* red  = (float*)(smem + S_RED);

    if (tid < NA) { bsm[tid] = bias[tid]; usm[tid] = u[tid]; winv[tid] = g_winv[tid]; }
    if (tid < TS) red[tid] = 0.0f;

    const float* xb = x + ((size_t)b * NS + tile * TS) * ND;

    // ---- x load / quantize+split staging: 4 threads per row ----
    const int xrow = tid >> 2;       // 0..127
    const int xseg = tid & 3;        // 8-float segment
    float xv[8];
    auto load_x = [&](int c) {
        const float4* p = (const float4*)(xb + (size_t)xrow * ND + c * KC + xseg * 8);
        float4 a = p[0], bb = p[1];
        xv[0]=a.x; xv[1]=a.y; xv[2]=a.z; xv[3]=a.w;
        xv[4]=bb.x; xv[5]=bb.y; xv[6]=bb.z; xv[7]=bb.w;
    };
    auto quant_sts = [&](int buf) {
        float m = 0.0f;
#pragma unroll
        for (int j = 0; j < 8; j++) m = fmaxf(m, fabsf(xv[j]));
        m = fmaxf(m, __shfl_xor_sync(0xffffffffu, m, 1));
        m = fmaxf(m, __shfl_xor_sync(0xffffffffu, m, 2));
        m = fmaxf(m, 1e-30f);
        float s = __fdividef(32256.0f, m);
        if (xseg == 0) ((float*)(smem + S_SXI(buf)))[xrow] = m * (1.0f / 32256.0f);
        uint32_t hw[2], lw[2];
#pragma unroll
        for (int h = 0; h < 2; h++) {
            uint32_t hb = 0, lb = 0;
#pragma unroll
            for (int j = 0; j < 4; j++) {
                int X  = __float2int_rn(xv[h * 4 + j] * s);
                int hh = (X + 128) >> 8;
                int ll = X - (hh << 8);
                hb |= (uint32_t)(hh & 255) << (8 * j);
                lb |= (uint32_t)(ll & 255) << (8 * j);
            }
            hw[h] = hb; lw[h] = lb;
        }
        *(uint2*)(smem + S_AH(buf) + xrow * 48 + xseg * 8) = make_uint2(hw[0], hw[1]);
        *(uint2*)(smem + S_AL(buf) + xrow * 48 + xseg * 8) = make_uint2(lw[0], lw[1]);
    };
    auto cp_w = [&](int c, int buf) {     // 512 cp16: one per thread
        int cls = tid >> 8, t2 = tid & 255;
        int n = t2 >> 1, sg = t2 & 1;
        const char* src = (const char*)((cls ? g_w8l : g_w8h) + (size_t)c * NA * KC + n * KC) + sg * 16;
        cp16(smem + (cls ? S_BL(buf) : S_BH(buf)) + n * 48 + sg * 16, src);
        cp_commit();
    };

    float facc[8][4];
#pragma unroll
    for (int nf = 0; nf < 8; nf++)
#pragma unroll
        for (int e = 0; e < 4; e++) facc[nf][e] = 0.0f;

    // ldmatrix lane addressing
    const int la_off = ((l & 7) + ((l >> 3) & 1) * 8) * 48 + (l >> 4) * 16;       // A
    const int lb_off = ((l & 7) + ((l >> 4) & 1) * 8) * 48 + ((l >> 3) & 1) * 16; // B
    const int g = l >> 2, tig = l & 3;
    const int r0 = wm * 16 + g, r1 = r0 + 8;

    // ---- prologue ----
    load_x(0);
    cp_w(0, 0);
    quant_sts(0);

#pragma unroll 1
    for (int c = 0; c < NCHUNK; c++) {
        const int buf = c & 1;
        if (c < NCHUNK - 1) { cp_w(c + 1, buf ^ 1); load_x(c + 1); cp_wait<1>(); }
        else cp_wait<0>();
        __syncthreads();

        const float* sxi = (const float*)(smem + S_SXI(buf));
        const float k1a = 65536.0f * sxi[r0];
        const float k1b = 65536.0f * sxi[r1];
        const float k2a = k1a * (1.0f / 256.0f);
        const float k2b = k1b * (1.0f / 256.0f);

        uint32_t ah[4], al[4];
        LDSM4(ah, smb + S_AH(buf) + wm * 16 * 48 + la_off);
        LDSM4(al, smb + S_AL(buf) + wm * 16 * 48 + la_off);

#pragma unroll
        for (int pair = 0; pair < 4; pair++) {
            uint32_t bh[4], bl[4];
            const uint32_t bb = (uint32_t)((wn * 64 + pair * 16) * 48) + lb_off;
            LDSM4(bh, smb + S_BH(buf) + bb);
            LDSM4(bl, smb + S_BL(buf) + bb);
#pragma unroll
            for (int q = 0; q < 2; q++) {
                const int nf = pair * 2 + q;
                int d[4];
                MMA_S8_ZERO(d, ah, bh[2 * q], bh[2 * q + 1]);          // hi*hi
                facc[nf][0] += (float)d[0] * k1a;
                facc[nf][1] += (float)d[1] * k1a;
                facc[nf][2] += (float)d[2] * k1b;
                facc[nf][3] += (float)d[3] * k1b;
                MMA_S8_ZERO(d, ah, bl[2 * q], bl[2 * q + 1]);          // hi*lo
                MMA_S8_ACC (d, al, bh[2 * q], bh[2 * q + 1]);          // + lo*hi
                facc[nf][0] += (float)d[0] * k2a;
                facc[nf][1] += (float)d[1] * k2a;
                facc[nf][2] += (float)d[2] * k2b;
                facc[nf][3] += (float)d[3] * k2b;
            }
        }
        if (c < NCHUNK - 1) quant_sts(buf ^ 1);
        __syncthreads();
    }

    // ---- epilogue: descale W, bias, tanh, dot(u) ----
    {
        float pA = 0.0f, pB = 0.0f;
#pragma unroll
        for (int nf = 0; nf < 8; nf++)
#pragma unroll
            for (int e = 0; e < 4; e++) {
                int col = wn * 64 + nf * 8 + 2 * tig + (e & 1);
                float val = facc[nf][e] * winv[col] + bsm[col];
                float t = fast_tanh(val) * usm[col];
                if (e < 2) pA += t; else pB += t;
            }
        pA += __shfl_xor_sync(0xffffffffu, pA, 1);
        pA += __shfl_xor_sync(0xffffffffu, pA, 2);
        pB += __shfl_xor_sync(0xffffffffu, pB, 1);
        pB += __shfl_xor_sync(0xffffffffu, pB, 2);
        if (tig == 0) {
            atomicAdd(&red[r0], pA);   // exactly 2 contributors/row (wn=0,1)
            atomicAdd(&red[r1], pB);
        }
    }
    __syncthreads();
    if (tid < TS) es[tid] = expf(red[tid]);   // faithful: no max-subtraction
    __syncthreads();

    // tile exp-sum (deterministic tree)
    if (tid < 64) red[tid] = es[tid] + es[tid + 64];
    __syncthreads();
    if (tid < 32) {
        float v = red[tid] + red[tid + 32];
#pragma unroll
        for (int off = 16; off > 0; off >>= 1)
            v += __shfl_down_sync(0xffffffffu, v, off);
        if (tid == 0) g_esum[b * NTILE + tile] = v;
    }

    // weighted partial sum over tile rows, split across 2 thread-halves
    {
        float* scr = (float*)(smem + S_SCR);
        const int dcol = tid & 255;
        const int half = tid >> 8;
        float a0 = 0.0f, a1 = 0.0f;
        const int sbase = half * 64;
#pragma unroll 4
        for (int s = 0; s < 64; s += 2) {
            a0 += es[sbase + s]     * xb[(size_t)(sbase + s) * ND + dcol];
            a1 += es[sbase + s + 1] * xb[(size_t)(sbase + s + 1) * ND + dcol];
        }
        scr[half * 256 + dcol] = a0 + a1;
        __syncthreads();
        if (tid < 256)
            g_part[((size_t)b * NTILE + tile) * ND + tid] = scr[tid] + scr[256 + tid];
    }
}

// ---------------------------------------------------------------------------
__global__ void __launch_bounds__(256) finish_kernel(float* __restrict__ out)
{
    const int b = blockIdx.x;
    const int tid = threadIdx.x;
    float s = 0.f;
#pragma unroll
    for (int t = 0; t < NTILE; t++) s += g_esum[b * NTILE + t];
    const float inv = 1.0f / (s + 1e-8f);
    float v = 0.f;
#pragma unroll
    for (int t = 0; t < NTILE; t++) v += g_part[((size_t)b * NTILE + t) * ND + tid];
    out[b * ND + tid] = v * inv;
}

extern "C" void kernel_launch(void* const* d_in, const int* in_sizes, int n_in,
                              void* d_out, int out_size) {
    const float* x    = (const float*)d_in[0];
    const float* W    = (const float*)d_in[1];
    const float* bias = (const float*)d_in[2];
    const float* u    = (const float*)d_in[3];
    float* out        = (float*)d_out;

    cudaFuncSetAttribute(scores_kernel, cudaFuncAttributeMaxDynamicSharedMemorySize, SMEM_TOTAL);

    wprep_kernel<<<NA, 256>>>(W);
    scores_kernel<<<NB * NTILE, NT, SMEM_TOTAL>>>(x, bias, u);
    finish_kernel<<<NB, 256>>>(out);
}

// round 9
// speedup vs baseline: 1.1114x; 1.1114x over previous
#include <cuda_runtime.h>
#include <cuda_bf16.h>
#include <cstdint>

#define NB 256
#define NS 512
#define ND 256
#define NA 128
#define TS 128
#define NTILE 4
#define KC 16
#define NCHUNK 16

// ---- scratch (allocation-free rule: device globals) ----
__device__ float g_part[NB * NTILE * ND];
__device__ float g_esum[NB * NTILE];
__device__ __nv_bfloat16 g_wt_hi[NA * ND];   // [n][k] K-major
__device__ __nv_bfloat16 g_wt_lo[NA * ND];

// ---- smem layout (bytes) ----
#define S_ES   0
#define S_BSM  512
#define S_USM  1024
#define S_RED  1536
#define TILEB  31744
#define S_AH(b) (2048 + (b) * TILEB)         // 64 rows * 48B  (rows 0-63 bf16 hi)
#define S_AL(b) (S_AH(b) + 3072)             // lo
#define S_BH(b) (S_AH(b) + 6144)             // 128 n * 48B
#define S_BL(b) (S_AH(b) + 12288)
#define S_XF(b) (S_AH(b) + 18432)            // 64 rows * 80B fp32 (rows 64-127)
#define S_WF(b) (S_AH(b) + 23552)            // 16 k * 512B fp32
#define S_MAT  2048                           // 64*17 floats, reused post-loop
#define SMEM_TOTAL (2048 + 2 * TILEB)        // 65536

#define LDSM4(r, addr) \
    asm volatile("ldmatrix.sync.aligned.m8n8.x4.shared.b16 {%0,%1,%2,%3}, [%4];" \
        : "=r"((r)[0]), "=r"((r)[1]), "=r"((r)[2]), "=r"((r)[3]) : "r"(addr))

#define MMA16816(d, a, b0, b1) \
    asm volatile("mma.sync.aligned.m16n8k16.row.col.f32.bf16.bf16.f32 " \
        "{%0,%1,%2,%3},{%4,%5,%6,%7},{%8,%9},{%0,%1,%2,%3};" \
        : "+f"((d)[0]), "+f"((d)[1]), "+f"((d)[2]), "+f"((d)[3]) \
        : "r"((a)[0]), "r"((a)[1]), "r"((a)[2]), "r"((a)[3]), "r"(b0), "r"(b1))

__device__ __forceinline__ void cp16(char* dst, const char* src) {
    unsigned saddr = (unsigned)__cvta_generic_to_shared(dst);
    asm volatile("cp.async.cg.shared.global [%0], [%1], 16;\n" :: "r"(saddr), "l"(src));
}
__device__ __forceinline__ void cp_commit() { asm volatile("cp.async.commit_group;\n"); }
template<int N> __device__ __forceinline__ void cp_wait() {
    asm volatile("cp.async.wait_group %0;\n" :: "n"(N));
}
__device__ __forceinline__ uint32_t pack_bf2(float a, float b) {
    __nv_bfloat162 t = __halves2bfloat162(__float2bfloat16(a), __float2bfloat16(b));
    return *(uint32_t*)&t;
}
__device__ __forceinline__ unsigned long long pack2(float lo, float hi) {
    unsigned long long r;
    asm("mov.b64 %0, {%1, %2};" : "=l"(r) : "f"(lo), "f"(hi));
    return r;
}
__device__ __forceinline__ void unpack2(unsigned long long v, float& lo, float& hi) {
    asm("mov.b64 {%0, %1}, %2;" : "=f"(lo), "=f"(hi) : "l"(v));
}
// NON-volatile: ptxas may interleave these into MMA pipe shadows
__device__ __forceinline__ void ffma2(unsigned long long& acc, unsigned long long a, unsigned long long b) {
    asm("fma.rn.f32x2 %0, %1, %2, %0;" : "+l"(acc) : "l"(a), "l"(b));
}
__device__ __forceinline__ float fast_tanh(float x) {
    float e = __expf(2.0f * x);
    return 1.0f - __fdividef(2.0f, e + 1.0f);
}

// ---------------------------------------------------------------------------
__global__ void __launch_bounds__(256) wprep_kernel(const float* __restrict__ W) {
    int idx = blockIdx.x * 256 + threadIdx.x;
    if (idx < ND * NA) {
        int k = idx >> 7;
        int n = idx & (NA - 1);
        float w = W[idx];
        __nv_bfloat16 h = __float2bfloat16(w);
        g_wt_hi[n * ND + k] = h;
        g_wt_lo[n * ND + k] = __float2bfloat16(w - __bfloat162float(h));
    }
}

// ---------------------------------------------------------------------------
// Fine-grained dual-pipe: rows 0-63 HMMA 3-pass bf16, rows 64-127 exact FFMA2,
// interleaved at np-step granularity in one instruction stream.
// ---------------------------------------------------------------------------
__global__ void __launch_bounds__(256, 2) scores_kernel(
    const float* __restrict__ x, const float* __restrict__ W,
    const float* __restrict__ bias, const float* __restrict__ u)
{
    extern __shared__ char smem[];
    const uint32_t smb = (uint32_t)__cvta_generic_to_shared(smem);

    const int bid  = blockIdx.x;
    const int tile = bid & 3;
    const int b    = bid >> 2;
    const int tid  = threadIdx.x;
    const int w    = tid >> 5;
    const int l    = tid & 31;
    const int wm   = w >> 1;      // 0..3 : H rows wm*16
    const int wn   = w & 1;       // 0..1 : H cols wn*64

    float* es  = (float*)(smem + S_ES);
    float* bsm = (float*)(smem + S_BSM);
    float* usm = (float*)(smem + S_USM);
    float* red = (float*)(smem + S_RED);

    if (tid < NA) { bsm[tid] = bias[tid]; usm[tid] = u[tid]; }
    if (tid < TS) red[tid] = 0.0f;

    const float* xb = x + ((size_t)b * NS + tile * TS) * ND;

    // ---- A staging (rows 0-63): 4 threads/row, LDG->convert->STS ----
    const int xrow = tid >> 2, xseg = tid & 3;
    float4 st;
    auto load_x = [&](int c) {
        st = *(const float4*)(xb + (size_t)xrow * ND + c * KC + xseg * 4);
    };
    auto sts_x = [&](int buf) {
        float vs[4] = { st.x, st.y, st.z, st.w };
        float ls[4];
#pragma unroll
        for (int j = 0; j < 4; j++) {
            __nv_bfloat16 h = __float2bfloat16(vs[j]);
            ls[j] = vs[j] - __bfloat162float(h);
        }
        int off = xrow * 48 + xseg * 8;
        *(uint2*)(smem + S_AH(buf) + off) = make_uint2(pack_bf2(vs[0], vs[1]), pack_bf2(vs[2], vs[3]));
        *(uint2*)(smem + S_AL(buf) + off) = make_uint2(pack_bf2(ls[0], ls[1]), pack_bf2(ls[2], ls[3]));
    };
    // ---- cp.async staging: XF (rows 64-127 fp32), B bf16 hi/lo, WF fp32 ----
    auto issue_async = [&](int c, int buf) {
        {   // XF: 256 cp16
            int row = tid >> 2, seg = tid & 3;
            cp16(smem + S_XF(buf) + row * 80 + seg * 16,
                 (const char*)(xb + (size_t)(64 + row) * ND + c * KC + seg * 4));
        }
#pragma unroll
        for (int it = 0; it < 2; it++) {     // B: 512 cp16
            int idx = tid + it * 256;
            int cls = idx >> 8, rem = idx & 255;
            int n = rem >> 1, sg = rem & 1;
            const char* src = (const char*)((cls ? g_wt_lo : g_wt_hi) + (size_t)n * ND + c * KC) + sg * 16;
            cp16(smem + (cls ? S_BL(buf) : S_BH(buf)) + n * 48 + sg * 16, src);
        }
#pragma unroll
        for (int it = 0; it < 2; it++) {     // WF: 512 cp16
            int idx = tid + it * 256;
            int k = idx >> 5, seg = idx & 31;
            cp16(smem + S_WF(buf) + k * 512 + seg * 16,
                 (const char*)(W + (size_t)(c * KC + k) * NA + seg * 4));
        }
        cp_commit();
    };

    // H accumulators: warp tile 16M x 64N -> acc[8 nf][4]
    float acc[8][4];
#pragma unroll
    for (int nf = 0; nf < 8; nf++)
#pragma unroll
        for (int e = 0; e < 4; e++) acc[nf][e] = 0.0f;

    // F accumulators: thread tile 4 rows x 8 cols (rows 64+4*ty.., cols 8*tx..)
    const int ty = tid >> 4, tx = tid & 15;
    unsigned long long acc2[4][4];
#pragma unroll
    for (int i = 0; i < 4; i++)
#pragma unroll
        for (int p = 0; p < 4; p++) acc2[i][p] = 0ull;

    const uint32_t lane_off = (uint32_t)((l & 15) * 48 + (l >> 4) * 16);

    // ---- prologue ----
    load_x(0);
    issue_async(0, 0);
    sts_x(0);

#pragma unroll 1
    for (int c = 0; c < NCHUNK; c++) {
        const int buf = c & 1;
        if (c < NCHUNK - 1) { issue_async(c + 1, buf ^ 1); load_x(c + 1); cp_wait<1>(); }
        else cp_wait<0>();
        __syncthreads();

        const uint32_t ah_base = smb + S_AH(buf) + (uint32_t)(wm * 16) * 48 + lane_off;
        const uint32_t al_base = smb + S_AL(buf) + (uint32_t)(wm * 16) * 48 + lane_off;
        const float* xf = (const float*)(smem + S_XF(buf));
        const float* wf = (const float*)(smem + S_WF(buf));

        uint32_t ah[4], al[4];
        LDSM4(ah, ah_base);
        LDSM4(al, al_base);

#pragma unroll
        for (int np = 0; np < 4; np++) {
            // --- H: 6 MMAs on 16x16 B block np ---
            uint32_t bh[4], bl[4];
            const uint32_t bb = (uint32_t)((wn * 64 + np * 16) * 48) + lane_off;
            LDSM4(bh, smb + S_BH(buf) + bb);
            LDSM4(bl, smb + S_BL(buf) + bb);
#pragma unroll
            for (int sn = 0; sn < 2; sn++) {
                float* d = acc[np * 2 + sn];
                uint32_t h0 = sn ? bh[1] : bh[0], h1 = sn ? bh[3] : bh[2];
                uint32_t l0 = sn ? bl[1] : bl[0], l1 = sn ? bl[3] : bl[2];
                MMA16816(d, ah, h0, h1);
                MMA16816(d, ah, l0, l1);
                MMA16816(d, al, h0, h1);
            }
            // --- F: 2 kk-pairs of exact fp32 work (non-volatile -> fills MMA shadows) ---
#pragma unroll
            for (int t = 0; t < 2; t++) {
                const int kk = (np * 2 + t) * 2;
                float2 ax[4];
#pragma unroll
                for (int i = 0; i < 4; i++)
                    ax[i] = *(const float2*)(xf + (ty * 4 + i) * 20 + kk);
#pragma unroll
                for (int sub = 0; sub < 2; sub++) {
                    const unsigned long long* wr =
                        (const unsigned long long*)(wf + (kk + sub) * NA + tx * 8);
                    unsigned long long wp0 = wr[0], wp1 = wr[1], wp2 = wr[2], wp3 = wr[3];
#pragma unroll
                    for (int i = 0; i < 4; i++) {
                        float a = sub ? ax[i].y : ax[i].x;
                        unsigned long long ap = pack2(a, a);
                        ffma2(acc2[i][0], ap, wp0);
                        ffma2(acc2[i][1], ap, wp1);
                        ffma2(acc2[i][2], ap, wp2);
                        ffma2(acc2[i][3], ap, wp3);
                    }
                }
            }
        }
        if (c < NCHUNK - 1) sts_x(buf ^ 1);
        __syncthreads();
    }

    // ---- H epilogue: rows 0-63 ----
    {
        const int g = l >> 2, tig = l & 3;
        float pA = 0.0f, pB = 0.0f;
#pragma unroll
        for (int nf = 0; nf < 8; nf++)
#pragma unroll
            for (int e = 0; e < 2; e++) {
                int col = wn * 64 + nf * 8 + 2 * tig + e;
                pA += fast_tanh(acc[nf][e]     + bsm[col]) * usm[col];
                pB += fast_tanh(acc[nf][2 + e] + bsm[col]) * usm[col];
            }
        pA += __shfl_xor_sync(0xffffffffu, pA, 1);
        pA += __shfl_xor_sync(0xffffffffu, pA, 2);
        pB += __shfl_xor_sync(0xffffffffu, pB, 1);
        pB += __shfl_xor_sync(0xffffffffu, pB, 2);
        if (tig == 0) {
            atomicAdd(&red[wm * 16 + g], pA);       // exactly 2 contributors/row
            atomicAdd(&red[wm * 16 + 8 + g], pB);
        }
    }
    __syncthreads();          // A/XF buffers dead; reuse as mat
    // ---- F epilogue: rows 64-127 ----
    {
        float* mat = (float*)(smem + S_MAT);        // 64 x 17
#pragma unroll
        for (int i = 0; i < 4; i++) {
            float partial = 0.0f;
#pragma unroll
            for (int p = 0; p < 4; p++) {
                float lo, hi; unpack2(acc2[i][p], lo, hi);
                int c0 = 8 * tx + 2 * p;
                partial += fast_tanh(lo + bsm[c0])     * usm[c0];
                partial += fast_tanh(hi + bsm[c0 + 1]) * usm[c0 + 1];
            }
            mat[(ty * 4 + i) * 17 + tx] = partial;
        }
    }
    __syncthreads();
    if (tid < 64) {
        const float* mat = (const float*)(smem + S_MAT);
        float lg = 0.0f;
#pragma unroll
        for (int j = 0; j < 16; j++) lg += mat[tid * 17 + j];
        red[64 + tid] = lg;
    }
    __syncthreads();
    if (tid < TS) es[tid] = expf(red[tid]);         // faithful: no max-subtraction
    __syncthreads();

    // tile exp-sum (deterministic tree)
    if (tid < 64) red[tid] = es[tid] + es[tid + 64];
    __syncthreads();
    if (tid < 32) {
        float v = red[tid] + red[tid + 32];
#pragma unroll
        for (int off = 16; off > 0; off >>= 1)
            v += __shfl_down_sync(0xffffffffu, v, off);
        if (tid == 0) g_esum[b * NTILE + tile] = v;
    }

    // weighted partial sum over tile rows (x L2-hot)
    float a0 = 0.f, a1 = 0.f, a2 = 0.f, a3 = 0.f;
#pragma unroll 4
    for (int s = 0; s < TS; s += 4) {
        a0 += es[s + 0] * xb[(size_t)(s + 0) * ND + tid];
        a1 += es[s + 1] * xb[(size_t)(s + 1) * ND + tid];
        a2 += es[s + 2] * xb[(size_t)(s + 2) * ND + tid];
        a3 += es[s + 3] * xb[(size_t)(s + 3) * ND + tid];
    }
    g_part[((size_t)b * NTILE + tile) * ND + tid] = (a0 + a1) + (a2 + a3);
}

// ---------------------------------------------------------------------------
__global__ void __launch_bounds__(256) finish_kernel(float* __restrict__ out)
{
    const int b = blockIdx.x;
    const int tid = threadIdx.x;
    float s = 0.f;
#pragma unroll
    for (int t = 0; t < NTILE; t++) s += g_esum[b * NTILE + t];
    const float inv = 1.0f / (s + 1e-8f);
    float v = 0.f;
#pragma unroll
    for (int t = 0; t < NTILE; t++) v += g_part[((size_t)b * NTILE + t) * ND + tid];
    out[b * ND + tid] = v * inv;
}

extern "C" void kernel_launch(void* const* d_in, const int* in_sizes, int n_in,
                              void* d_out, int out_size) {
    const float* x    = (const float*)d_in[0];
    const float* W    = (const float*)d_in[1];
    const float* bias = (const float*)d_in[2];
    const float* u    = (const float*)d_in[3];
    float* out        = (float*)d_out;

    cudaFuncSetAttribute(scores_kernel, cudaFuncAttributeMaxDynamicSharedMemorySize, SMEM_TOTAL);

    wprep_kernel<<<(ND * NA + 255) / 256, 256>>>(W);
    scores_kernel<<<NB * NTILE, 256, SMEM_TOTAL>>>(x, W, bias, u);
    finish_kernel<<<NB, 256>>>(out);
}

// round 10
// speedup vs baseline: 1.9702x; 1.7727x over previous
#include <cuda_runtime.h>
#include <cuda_bf16.h>
#include <cstdint>

#define NB 256
#define NS 512
#define ND 256
#define NA 128
#define TS 128
#define NTILE 4
#define KC 32
#define NCHUNK 8
#define ASTR 40              // A bf16 row stride (elems) = 80B, ldmatrix conflict-free
#define BSTR 272             // B bf16 [k][n] row stride bytes (256 + 16 pad)

// ---- scratch (allocation-free rule: device globals) ----
__device__ float g_part[NB * NTILE * ND];
__device__ float g_esum[NB * NTILE];
__device__ int   g_cnt[NB];          // zero-init; reset each launch by combiner

// ---- smem layout (bytes) ----
#define S_ES   0
#define S_BSM  512
#define S_USM  1024
#define S_RED  1536
#define S_AH(b) (2048 + (b) * 20480)          // 128 rows * 80B
#define S_AL(b) (S_AH(b) + 10240)
#define S_BH(b) (43008 + (b) * 17408)         // 32 k-rows * 272B
#define S_BL(b) (S_BH(b) + 8704)
#define S_WF(b) (77824 + (b) * 16384)         // 32 k-rows * 512B fp32
#define SMEM_TOTAL 110592

#define LDSM4(r, addr) \
    asm volatile("ldmatrix.sync.aligned.m8n8.x4.shared.b16 {%0,%1,%2,%3}, [%4];" \
        : "=r"((r)[0]), "=r"((r)[1]), "=r"((r)[2]), "=r"((r)[3]) : "r"(addr))

#define LDSM4T(r, addr) \
    asm volatile("ldmatrix.sync.aligned.m8n8.x4.trans.shared.b16 {%0,%1,%2,%3}, [%4];" \
        : "=r"((r)[0]), "=r"((r)[1]), "=r"((r)[2]), "=r"((r)[3]) : "r"(addr))

#define MMA16816(d, a, b0, b1) \
    asm volatile("mma.sync.aligned.m16n8k16.row.col.f32.bf16.bf16.f32 " \
        "{%0,%1,%2,%3},{%4,%5,%6,%7},{%8,%9},{%0,%1,%2,%3};" \
        : "+f"((d)[0]), "+f"((d)[1]), "+f"((d)[2]), "+f"((d)[3]) \
        : "r"((a)[0]), "r"((a)[1]), "r"((a)[2]), "r"((a)[3]), "r"(b0), "r"(b1))

__device__ __forceinline__ void cp16(char* dst, const char* src) {
    unsigned saddr = (unsigned)__cvta_generic_to_shared(dst);
    asm volatile("cp.async.cg.shared.global [%0], [%1], 16;\n" :: "r"(saddr), "l"(src));
}
__device__ __forceinline__ void cp_commit() { asm volatile("cp.async.commit_group;\n"); }
template<int N> __device__ __forceinline__ void cp_wait() {
    asm volatile("cp.async.wait_group %0;\n" :: "n"(N));
}
__device__ __forceinline__ uint32_t pack_bf2(float a, float b) {
    __nv_bfloat162 t = __halves2bfloat162(__float2bfloat16(a), __float2bfloat16(b));
    return *(uint32_t*)&t;
}
__device__ __forceinline__ float bf_res(float v) {   // v - bf16(v)
    return v - __bfloat162float(__float2bfloat16(v));
}
__device__ __forceinline__ float fast_tanh(float x) {
    float e = __expf(2.0f * x);
    return 1.0f - __fdividef(2.0f, e + 1.0f);
}

// ---------------------------------------------------------------------------
// Single fused kernel: 3-pass bf16 HMMA GEMM (in-kernel W split via
// ldmatrix.trans), tanh/dot(u)/exp, weighted partial sum, and last-CTA
// per-batch deterministic combine.
// ---------------------------------------------------------------------------
__global__ void __launch_bounds__(256, 2) scores_kernel(
    const float* __restrict__ x, const float* __restrict__ W,
    const float* __restrict__ bias, const float* __restrict__ u,
    float* __restrict__ out)
{
    extern __shared__ char smem[];
    const uint32_t smb = (uint32_t)__cvta_generic_to_shared(smem);

    const int bid  = blockIdx.x;
    const int tile = bid & 3;
    const int b    = bid >> 2;
    const int tid  = threadIdx.x;
    const int w    = tid >> 5;
    const int l    = tid & 31;
    const int wm   = w >> 1;      // 0..3 : rows wm*32
    const int wn   = w & 1;       // 0..1 : cols wn*64

    float* es  = (float*)(smem + S_ES);
    float* bsm = (float*)(smem + S_BSM);
    float* usm = (float*)(smem + S_USM);
    float* red = (float*)(smem + S_RED);
    __shared__ int last_flag;

    if (tid < NA) { bsm[tid] = bias[tid]; usm[tid] = u[tid]; }
    if (tid < TS) red[tid] = 0.0f;

    const float* xb = x + ((size_t)b * NS + tile * TS) * ND;

    // ---- A staging: 2 threads/row, LDG->split->STS (round-4 verified) ----
    const int xrow = tid >> 1, xcolh = tid & 1;
    float4 st[4];
    auto load_x = [&](int c) {
        const float* p = xb + (size_t)xrow * ND + c * KC + xcolh * 16;
#pragma unroll
        for (int i = 0; i < 4; i++) st[i] = ((const float4*)p)[i];
    };
    auto sts_x = [&](int buf) {
        uint32_t hv[8], lv[8];
#pragma unroll
        for (int i = 0; i < 4; i++) {
            float vs[4] = { st[i].x, st[i].y, st[i].z, st[i].w };
            hv[2*i]   = pack_bf2(vs[0], vs[1]);
            hv[2*i+1] = pack_bf2(vs[2], vs[3]);
            lv[2*i]   = pack_bf2(bf_res(vs[0]), bf_res(vs[1]));
            lv[2*i+1] = pack_bf2(bf_res(vs[2]), bf_res(vs[3]));
        }
        int off = xrow * (ASTR * 2) + xcolh * 32;
        *(uint4*)(smem + S_AH(buf) + off)      = make_uint4(hv[0], hv[1], hv[2], hv[3]);
        *(uint4*)(smem + S_AH(buf) + off + 16) = make_uint4(hv[4], hv[5], hv[6], hv[7]);
        *(uint4*)(smem + S_AL(buf) + off)      = make_uint4(lv[0], lv[1], lv[2], lv[3]);
        *(uint4*)(smem + S_AL(buf) + off + 16) = make_uint4(lv[4], lv[5], lv[6], lv[7]);
    };
    // ---- W fp32 chunk staging via cp.async: [k=32][n=128] ----
    const int wk = tid >> 3, wseg0 = tid & 7;
    auto issue_w = [&](int c, int buf) {
#pragma unroll
        for (int j = 0; j < 4; j++) {
            int seg = wseg0 + 8 * j;
            cp16(smem + S_WF(buf) + wk * 512 + seg * 16,
                 (const char*)(W + (size_t)(c * KC + wk) * NA) + seg * 16);
        }
        cp_commit();
    };
    // ---- in-kernel W split fp32 -> bf16 hi/lo, [k][n] layout ----
    auto convert_w = [&](int buf) {
        const float* ws = (const float*)(smem + S_WF(buf));
        char* bh = smem + S_BH(buf);
        char* bl = smem + S_BL(buf);
#pragma unroll
        for (int j = 0; j < 4; j++) {
            int seg = wseg0 + 8 * j;
            float4 v = *(const float4*)(ws + wk * 128 + seg * 4);
            *(uint2*)(bh + wk * BSTR + seg * 8) =
                make_uint2(pack_bf2(v.x, v.y), pack_bf2(v.z, v.w));
            *(uint2*)(bl + wk * BSTR + seg * 8) =
                make_uint2(pack_bf2(bf_res(v.x), bf_res(v.y)),
                           pack_bf2(bf_res(v.z), bf_res(v.w)));
        }
    };

    float acc[2][8][4];
#pragma unroll
    for (int m = 0; m < 2; m++)
#pragma unroll
        for (int nf = 0; nf < 8; nf++)
#pragma unroll
            for (int e = 0; e < 4; e++) acc[m][nf][e] = 0.0f;

    // A lane addressing (non-trans, round-4 verified)
    const uint32_t a_lane = (uint32_t)((l & 15) * (ASTR * 2) + (l >> 4) * 16);
    // B lane addressing for ldmatrix.trans on [k][n]:
    //   matrices: m0=(k0-7,nblk0) m1=(k0-7,nblk1) m2=(k8-15,nblk0) m3=(k8-15,nblk1)
    //   -> regs r0..r3 identical to round-4 non-trans delivery
    const uint32_t b_lane = (uint32_t)(((l & 7) + 8 * (l >> 4)) * BSTR + ((l >> 3) & 1) * 16);

    // ---- prologue ----
    load_x(0);
    issue_w(0, 0);
    sts_x(0);

#pragma unroll 1
    for (int c = 0; c < NCHUNK; c++) {
        const int buf = c & 1;
        if (c < NCHUNK - 1) { issue_w(c + 1, buf ^ 1); load_x(c + 1); cp_wait<1>(); }
        else cp_wait<0>();
        __syncthreads();
        convert_w(buf);
        __syncthreads();

        const uint32_t ah_base = smb + S_AH(buf) + (uint32_t)(wm * 32) * (ASTR * 2) + a_lane;
        const uint32_t al_base = smb + S_AL(buf) + (uint32_t)(wm * 32) * (ASTR * 2) + a_lane;
        const uint32_t bh_base = smb + S_BH(buf) + b_lane + (uint32_t)(wn * 128);
        const uint32_t bl_base = smb + S_BL(buf) + b_lane + (uint32_t)(wn * 128);

#pragma unroll
        for (int kk = 0; kk < KC; kk += 16) {
            uint32_t ah[2][4], al[2][4];
#pragma unroll
            for (int m = 0; m < 2; m++) {
                LDSM4(ah[m], ah_base + m * 16 * (ASTR * 2) + kk * 2);
                LDSM4(al[m], al_base + m * 16 * (ASTR * 2) + kk * 2);
            }
#pragma unroll
            for (int np = 0; np < 4; np++) {
                uint32_t bh[4], bl[4];
                LDSM4T(bh, bh_base + kk * BSTR + np * 32);
                LDSM4T(bl, bl_base + kk * BSTR + np * 32);
#pragma unroll
                for (int m = 0; m < 2; m++)
#pragma unroll
                    for (int sn = 0; sn < 2; sn++) {
                        float* d = acc[m][np * 2 + sn];
                        uint32_t h0 = sn ? bh[1] : bh[0], h1 = sn ? bh[3] : bh[2];
                        uint32_t l0 = sn ? bl[1] : bl[0], l1 = sn ? bl[3] : bl[2];
                        MMA16816(d, ah[m], h0, h1);
                        MMA16816(d, ah[m], l0, l1);
                        MMA16816(d, al[m], h0, h1);
                    }
            }
        }
        if (c < NCHUNK - 1) sts_x(buf ^ 1);
        __syncthreads();
    }

    // ---- epilogue: tanh + dot(u) -> logits ----
    {
        const int g = l >> 2, tig = l & 3;
#pragma unroll
        for (int m = 0; m < 2; m++) {
            float pA = 0.0f, pB = 0.0f;
#pragma unroll
            for (int nf = 0; nf < 8; nf++)
#pragma unroll
                for (int e = 0; e < 2; e++) {
                    int col = wn * 64 + nf * 8 + 2 * tig + e;
                    pA += fast_tanh(acc[m][nf][e]     + bsm[col]) * usm[col];
                    pB += fast_tanh(acc[m][nf][2 + e] + bsm[col]) * usm[col];
                }
            pA += __shfl_xor_sync(0xffffffffu, pA, 1);
            pA += __shfl_xor_sync(0xffffffffu, pA, 2);
            pB += __shfl_xor_sync(0xffffffffu, pB, 1);
            pB += __shfl_xor_sync(0xffffffffu, pB, 2);
            if (tig == 0) {
                int row = wm * 32 + m * 16 + g;
                atomicAdd(&red[row], pA);        // exactly 2 contributors/row
                atomicAdd(&red[row + 8], pB);
            }
        }
    }
    __syncthreads();
    if (tid < TS) es[tid] = expf(red[tid]);      // faithful: no max-subtraction
    __syncthreads();

    // tile exp-sum (deterministic tree)
    if (tid < 64) red[tid] = es[tid] + es[tid + 64];
    __syncthreads();
    if (tid < 32) {
        float v = red[tid] + red[tid + 32];
#pragma unroll
        for (int off = 16; off > 0; off >>= 1)
            v += __shfl_down_sync(0xffffffffu, v, off);
        if (tid == 0) g_esum[b * NTILE + tile] = v;
    }

    // weighted partial sum over tile rows (x L2-hot)
    float a0 = 0.f, a1 = 0.f, a2 = 0.f, a3 = 0.f;
#pragma unroll 4
    for (int s = 0; s < TS; s += 4) {
        a0 += es[s + 0] * xb[(size_t)(s + 0) * ND + tid];
        a1 += es[s + 1] * xb[(size_t)(s + 1) * ND + tid];
        a2 += es[s + 2] * xb[(size_t)(s + 2) * ND + tid];
        a3 += es[s + 3] * xb[(size_t)(s + 3) * ND + tid];
    }
    g_part[((size_t)b * NTILE + tile) * ND + tid] = (a0 + a1) + (a2 + a3);

    // ---- last CTA per batch combines (deterministic: fixed read order) ----
    __syncthreads();
    if (tid == 0) {
        __threadfence();
        last_flag = (atomicAdd(&g_cnt[b], 1) == NTILE - 1);
    }
    __syncthreads();
    if (last_flag) {
        __threadfence();
        float s = 0.f;
#pragma unroll
        for (int t = 0; t < NTILE; t++) s += __ldcg(&g_esum[b * NTILE + t]);
        const float inv = 1.0f / (s + 1e-8f);
        float v = 0.f;
#pragma unroll
        for (int t = 0; t < NTILE; t++)
            v += __ldcg(&g_part[((size_t)b * NTILE + t) * ND + tid]);
        out[b * ND + tid] = v * inv;
        if (tid == 0) g_cnt[b] = 0;              // reset for next graph replay
    }
}

extern "C" void kernel_launch(void* const* d_in, const int* in_sizes, int n_in,
                              void* d_out, int out_size) {
    const float* x    = (const float*)d_in[0];
    const float* W    = (const float*)d_in[1];
    const float* bias = (const float*)d_in[2];
    const float* u    = (const float*)d_in[3];
    float* out        = (float*)d_out;

    cudaFuncSetAttribute(scores_kernel, cudaFuncAttributeMaxDynamicSharedMemorySize, SMEM_TOTAL);
    scores_kernel<<<NB * NTILE, 256, SMEM_TOTAL>>>(x, W, bias, u, out);
}

// round 11
// speedup vs baseline: 2.1961x; 1.1146x over previous
#include <cuda_runtime.h>
#include <cuda_bf16.h>
#include <cstdint>

#define NB 256
#define NS 512
#define ND 256
#define NA 128
#define TS 128
#define NTILE 4
#define KC 32
#define NCHUNK 8
#define ASTRB 144            // A fp32 smem row stride bytes (16B-aligned, 2-way LDS worst case)
#define BSTRB 80             // B bf16 row stride bytes (ldmatrix conflict-free)

// ---- scratch (allocation-free rule: device globals) ----
__device__ float g_part[NB * NTILE * ND];
__device__ float g_esum[NB * NTILE];
__device__ int   g_cnt[NB];                 // zero-init; combiner resets each launch
__device__ __nv_bfloat16 g_wt_hi[NA * ND];  // [n][k] K-major
__device__ __nv_bfloat16 g_wt_lo[NA * ND];

// ---- smem layout (bytes) ----
#define S_ES   0
#define S_BSM  512
#define S_USM  1024
#define S_RED  1536
#define S_A(st) (2048 + (st) * (TS * ASTRB))          // 3 stages x 18432
#define S_BH(b) (57344 + (b) * 20480)                 // 2 stages x (hi+lo)
#define S_BL(b) (S_BH(b) + 10240)
#define SMEM_TOTAL 98304

#define LDSM4(r, addr) \
    asm volatile("ldmatrix.sync.aligned.m8n8.x4.shared.b16 {%0,%1,%2,%3}, [%4];" \
        : "=r"((r)[0]), "=r"((r)[1]), "=r"((r)[2]), "=r"((r)[3]) : "r"(addr))

#define MMA16816(d, a, b0, b1) \
    asm volatile("mma.sync.aligned.m16n8k16.row.col.f32.bf16.bf16.f32 " \
        "{%0,%1,%2,%3},{%4,%5,%6,%7},{%8,%9},{%0,%1,%2,%3};" \
        : "+f"((d)[0]), "+f"((d)[1]), "+f"((d)[2]), "+f"((d)[3]) \
        : "r"((a)[0]), "r"((a)[1]), "r"((a)[2]), "r"((a)[3]), "r"(b0), "r"(b1))

__device__ __forceinline__ void cp16(uint32_t dst, const char* src) {
    asm volatile("cp.async.cg.shared.global [%0], [%1], 16;\n" :: "r"(dst), "l"(src));
}
__device__ __forceinline__ void cp_commit() { asm volatile("cp.async.commit_group;\n"); }
template<int N> __device__ __forceinline__ void cp_wait() {
    asm volatile("cp.async.wait_group %0;\n" :: "n"(N));
}
__device__ __forceinline__ uint32_t pack_bf2(float a, float b) {
    __nv_bfloat162 t = __halves2bfloat162(__float2bfloat16(a), __float2bfloat16(b));
    return *(uint32_t*)&t;
}
__device__ __forceinline__ float bf_res(float v) {
    return v - __bfloat162float(__float2bfloat16(v));
}
__device__ __forceinline__ float fast_tanh(float x) {
    float e = __expf(2.0f * x);
    return 1.0f - __fdividef(2.0f, e + 1.0f);
}

// ---------------------------------------------------------------------------
__global__ void __launch_bounds__(256) wprep_kernel(const float* __restrict__ W) {
    int idx = blockIdx.x * 256 + threadIdx.x;
    if (idx < ND * NA) {
        int k = idx >> 7;
        int n = idx & (NA - 1);
        float w = W[idx];
        __nv_bfloat16 h = __float2bfloat16(w);
        g_wt_hi[n * ND + k] = h;
        g_wt_lo[n * ND + k] = __float2bfloat16(w - __bfloat162float(h));
    }
}

// ---------------------------------------------------------------------------
// Fused scores + combine.  A: fp32 cp.async 3-stage -> per-lane LDS.64 ->
// in-register bf16 split (no STS/ldmatrix).  B: pre-split bf16, 2-stage,
// LDSM4.  One __syncthreads per chunk.
// ---------------------------------------------------------------------------
__global__ void __launch_bounds__(256, 2) scores_kernel(
    const float* __restrict__ x, const float* __restrict__ bias,
    const float* __restrict__ u, float* __restrict__ out)
{
    extern __shared__ char smem[];
    const uint32_t smb = (uint32_t)__cvta_generic_to_shared(smem);

    const int bid  = blockIdx.x;
    const int tile = bid & 3;
    const int b    = bid >> 2;
    const int tid  = threadIdx.x;
    const int w    = tid >> 5;
    const int l    = tid & 31;
    const int wm   = w >> 1;        // rows wm*32
    const int wn   = w & 1;         // cols wn*64
    const int gid  = l >> 2;        // 0..7
    const int j    = l & 3;

    float* es  = (float*)(smem + S_ES);
    float* bsm = (float*)(smem + S_BSM);
    float* usm = (float*)(smem + S_USM);
    float* red = (float*)(smem + S_RED);
    __shared__ int last_flag;

    if (tid < NA) { bsm[tid] = bias[tid]; usm[tid] = u[tid]; }
    if (tid < TS) red[tid] = 0.0f;

    const float* xb = x + ((size_t)b * NS + tile * TS) * ND;

    // ---- cp.async issuers ----
    auto issue_a = [&](int c) {       // A fp32 chunk c -> stage c%3
        const uint32_t base = smb + S_A(c % 3);
#pragma unroll
        for (int it = 0; it < 4; it++) {
            int idx = tid + it * 256;
            int row = idx >> 3, seg = idx & 7;
            cp16(base + row * ASTRB + seg * 16,
                 (const char*)(xb + (size_t)row * ND + c * KC + seg * 4));
        }
    };
    auto issue_b = [&](int c) {       // B bf16 hi/lo chunk c -> buf c&1
#pragma unroll
        for (int it = 0; it < 4; it++) {
            int idx = tid + it * 256;
            int cls = idx >> 9, rem = idx & 511;
            int n = rem >> 2, s = rem & 3;
            const char* src = (const char*)((cls ? g_wt_lo : g_wt_hi)
                               + (size_t)n * ND + c * KC) + s * 16;
            cp16(smb + (cls ? S_BL(c & 1) : S_BH(c & 1)) + n * BSTRB + s * 16, src);
        }
    };

    float acc[2][8][4];
#pragma unroll
    for (int m = 0; m < 2; m++)
#pragma unroll
        for (int nf = 0; nf < 8; nf++)
#pragma unroll
            for (int e = 0; e < 4; e++) acc[m][nf][e] = 0.0f;

    const uint32_t b_lane = (uint32_t)((l & 15) * BSTRB + (l >> 4) * 16);

    // ---- prologue: G_{-2} = A(0);  G_{-1} = A(1) + B(0) ----
    issue_a(0); cp_commit();
    issue_a(1); issue_b(0); cp_commit();

#pragma unroll 1
    for (int c = 0; c < NCHUNK; c++) {
        __syncthreads();                       // all reads of old buffers done
        if (c < NCHUNK - 2)      { issue_a(c + 2); issue_b(c + 1); cp_commit(); cp_wait<1>(); }
        else if (c == NCHUNK - 2){ issue_b(c + 1); cp_commit(); cp_wait<1>(); }
        else                     { cp_wait<0>(); }
        __syncthreads();                       // staged data visible to all

        const uint32_t a_base  = smb + S_A(c % 3) + (uint32_t)(wm * 32 + gid) * ASTRB + (uint32_t)(j * 8);
        const uint32_t bh_base = smb + S_BH(c & 1) + (uint32_t)(wn * 64) * BSTRB + b_lane;
        const uint32_t bl_base = smb + S_BL(c & 1) + (uint32_t)(wn * 64) * BSTRB + b_lane;

#pragma unroll
        for (int kk = 0; kk < KC; kk += 16) {
            uint32_t ah[2][4], al[2][4];
#pragma unroll
            for (int m = 0; m < 2; m++) {
                const uint32_t ra = a_base + (uint32_t)(m * 16) * ASTRB + (uint32_t)(kk * 4);
                float2 f0, f1, f2, f3;
                asm volatile("ld.shared.v2.f32 {%0,%1}, [%2];" : "=f"(f0.x), "=f"(f0.y) : "r"(ra));
                asm volatile("ld.shared.v2.f32 {%0,%1}, [%2];" : "=f"(f1.x), "=f"(f1.y) : "r"(ra + 8 * ASTRB));
                asm volatile("ld.shared.v2.f32 {%0,%1}, [%2];" : "=f"(f2.x), "=f"(f2.y) : "r"(ra + 32));
                asm volatile("ld.shared.v2.f32 {%0,%1}, [%2];" : "=f"(f3.x), "=f"(f3.y) : "r"(ra + 8 * ASTRB + 32));
                ah[m][0] = pack_bf2(f0.x, f0.y); al[m][0] = pack_bf2(bf_res(f0.x), bf_res(f0.y));
                ah[m][1] = pack_bf2(f1.x, f1.y); al[m][1] = pack_bf2(bf_res(f1.x), bf_res(f1.y));
                ah[m][2] = pack_bf2(f2.x, f2.y); al[m][2] = pack_bf2(bf_res(f2.x), bf_res(f2.y));
                ah[m][3] = pack_bf2(f3.x, f3.y); al[m][3] = pack_bf2(bf_res(f3.x), bf_res(f3.y));
            }
#pragma unroll
            for (int np = 0; np < 4; np++) {
                uint32_t bh[4], bl[4];
                LDSM4(bh, bh_base + (uint32_t)(np * 16) * BSTRB + (uint32_t)(kk * 2));
                LDSM4(bl, bl_base + (uint32_t)(np * 16) * BSTRB + (uint32_t)(kk * 2));
#pragma unroll
                for (int m = 0; m < 2; m++)
#pragma unroll
                    for (int sn = 0; sn < 2; sn++) {
                        float* d = acc[m][np * 2 + sn];
                        uint32_t h0 = sn ? bh[1] : bh[0], h1 = sn ? bh[3] : bh[2];
                        uint32_t l0 = sn ? bl[1] : bl[0], l1 = sn ? bl[3] : bl[2];
                        MMA16816(d, ah[m], h0, h1);
                        MMA16816(d, ah[m], l0, l1);
                        MMA16816(d, al[m], h0, h1);
                    }
            }
        }
    }

    // ---- epilogue: tanh + dot(u) -> logits ----
    {
        const int tig = j;
#pragma unroll
        for (int m = 0; m < 2; m++) {
            float pA = 0.0f, pB = 0.0f;
#pragma unroll
            for (int nf = 0; nf < 8; nf++)
#pragma unroll
                for (int e = 0; e < 2; e++) {
                    int col = wn * 64 + nf * 8 + 2 * tig + e;
                    pA += fast_tanh(acc[m][nf][e]     + bsm[col]) * usm[col];
                    pB += fast_tanh(acc[m][nf][2 + e] + bsm[col]) * usm[col];
                }
            pA += __shfl_xor_sync(0xffffffffu, pA, 1);
            pA += __shfl_xor_sync(0xffffffffu, pA, 2);
            pB += __shfl_xor_sync(0xffffffffu, pB, 1);
            pB += __shfl_xor_sync(0xffffffffu, pB, 2);
            if (tig == 0) {
                int row = wm * 32 + m * 16 + gid;
                atomicAdd(&red[row], pA);        // exactly 2 contributors/row
                atomicAdd(&red[row + 8], pB);
            }
        }
    }
    __syncthreads();
    if (tid < TS) es[tid] = expf(red[tid]);      // faithful: no max-subtraction
    __syncthreads();

    // tile exp-sum (deterministic tree)
    if (tid < 64) red[tid] = es[tid] + es[tid + 64];
    __syncthreads();
    if (tid < 32) {
        float v = red[tid] + red[tid + 32];
#pragma unroll
        for (int off = 16; off > 0; off >>= 1)
            v += __shfl_down_sync(0xffffffffu, v, off);
        if (tid == 0) g_esum[b * NTILE + tile] = v;
    }

    // weighted partial sum over tile rows (x L2-hot)
    float a0 = 0.f, a1 = 0.f, a2 = 0.f, a3 = 0.f;
#pragma unroll 4
    for (int s = 0; s < TS; s += 4) {
        a0 += es[s + 0] * xb[(size_t)(s + 0) * ND + tid];
        a1 += es[s + 1] * xb[(size_t)(s + 1) * ND + tid];
        a2 += es[s + 2] * xb[(size_t)(s + 2) * ND + tid];
        a3 += es[s + 3] * xb[(size_t)(s + 3) * ND + tid];
    }
    g_part[((size_t)b * NTILE + tile) * ND + tid] = (a0 + a1) + (a2 + a3);

    // ---- last CTA per batch combines (deterministic fixed-order reads) ----
    __syncthreads();
    if (tid == 0) {
        __threadfence();
        last_flag = (atomicAdd(&g_cnt[b], 1) == NTILE - 1);
    }
    __syncthreads();
    if (last_flag) {
        __threadfence();
        float s = 0.f;
#pragma unroll
        for (int t = 0; t < NTILE; t++) s += __ldcg(&g_esum[b * NTILE + t]);
        const float inv = 1.0f / (s + 1e-8f);
        float v = 0.f;
#pragma unroll
        for (int t = 0; t < NTILE; t++)
            v += __ldcg(&g_part[((size_t)b * NTILE + t) * ND + tid]);
        out[b * ND + tid] = v * inv;
        if (tid == 0) g_cnt[b] = 0;              // reset for next graph replay
    }
}

extern "C" void kernel_launch(void* const* d_in, const int* in_sizes, int n_in,
                              void* d_out, int out_size) {
    const float* x    = (const float*)d_in[0];
    const float* W    = (const float*)d_in[1];
    const float* bias = (const float*)d_in[2];
    const float* u    = (const float*)d_in[3];
    float* out        = (float*)d_out;

    cudaFuncSetAttribute(scores_kernel, cudaFuncAttributeMaxDynamicSharedMemorySize, SMEM_TOTAL);

    wprep_kernel<<<(ND * NA + 255) / 256, 256>>>(W);
    scores_kernel<<<NB * NTILE, 256, SMEM_TOTAL>>>(x, bias, u, out);
}